// round 17
// baseline (speedup 1.0000x reference)
#include <cuda_runtime.h>
#include <cstdint>
#include <cstddef>

// ---------------------------------------------------------------------------
// Problem constants
// ---------------------------------------------------------------------------
#define BB    256      // batch
#define SS    32       // seq len
#define II    128      // input dim
#define HH    256      // hidden
#define LBL   200      // label
#define NSUB  491
#define NSUBP 496      // NSUB padded to multiple of 4 floats
#define NATOMS 8000
#define NMOL  600

#define HPITCH 260     // h_s row pitch (floats): 16B-aligned, bank-staggered

// ---------------------------------------------------------------------------
// Scratch (static __device__ — no allocation anywhere)
// ---------------------------------------------------------------------------
__device__ __align__(16) float g_xp[2 * BB * SS * 3 * HH];
__device__ __align__(16) float g_h[2][2 * BB * HH];
__device__ int   g_idxlast[BB];
__device__ int   g_molstart[NMOL + 1];
__device__ int   g_bar[8 * 32];                        // 8 barrier groups, 128B apart
__device__ __align__(16) float g_pat[BB * 2 * HH];     // relu(h_last) written by GRU
__device__ __align__(16) float g_query[BB * HH];
__device__ __align__(16) float g_v[NATOMS * HH];
__device__ __align__(16) float g_hv[NATOMS * HH];
__device__ __align__(16) float g_molsumT[HH * NMOL];   // transposed [H][NMOL]
__device__ __align__(16) float g_emb[LBL * HH];
__device__ __align__(16) float g_match[BB * LBL];
__device__ __align__(16) float g_att[BB * LBL];
__device__ __align__(16) float g_bip[BB * NSUBP];      // padded stride
__device__ __align__(16) float g_wmT[LBL * NSUBP];     // masked weight, transposed+padded
__device__ __align__(16) float g_bbip[NSUBP];          // padded bias
// pre-transposed weights (all fast GEMMs are transB with K-contiguous rows)
__device__ __align__(16) float g_wqT[HH * 2 * HH];     // [256][512]
__device__ __align__(16) float g_wg0T[HH * HH];
__device__ __align__(16) float g_wg1T[HH * HH];
__device__ __align__(16) float g_wbipT[NSUBP * HH];    // [496][256], rows 491..495 zero

// ---------------------------------------------------------------------------
// Helpers
// ---------------------------------------------------------------------------
__device__ __forceinline__ unsigned long long ffma2(unsigned long long a,
                                                    unsigned long long b,
                                                    unsigned long long c) {
#if defined(__CUDA_ARCH__) && (__CUDA_ARCH__ >= 1000)
    unsigned long long d;
    asm("fma.rn.f32x2 %0, %1, %2, %3;" : "=l"(d) : "l"(a), "l"(b), "l"(c));
    return d;
#else
    float2 af = *reinterpret_cast<float2*>(&a);
    float2 bf = *reinterpret_cast<float2*>(&b);
    float2 cf = *reinterpret_cast<float2*>(&c);
    float2 df;
    df.x = fmaf(af.x, bf.x, cf.x);
    df.y = fmaf(af.y, bf.y, cf.y);
    return *reinterpret_cast<unsigned long long*>(&df);
#endif
}

__device__ __forceinline__ unsigned long long lds64(const float* p) {
    return *reinterpret_cast<const unsigned long long*>(p);
}

__device__ __forceinline__ float unpack_sum(unsigned long long u) {
    return __uint_as_float((unsigned)u) + __uint_as_float((unsigned)(u >> 32));
}

__device__ __forceinline__ float sigmoidf_(float x) {
    return 1.f / (1.f + expf(-x));
}

__device__ __forceinline__ void cp16(float* dst, const float* src, bool p) {
    unsigned s = (unsigned)__cvta_generic_to_shared(dst);
    int n = p ? 16 : 0;
    asm volatile("cp.async.ca.shared.global [%0], [%1], 16, %2;"
                 :: "r"(s), "l"(src), "r"(n));
}
__device__ __forceinline__ void cp8(float* dst, const float* src, bool p) {
    unsigned s = (unsigned)__cvta_generic_to_shared(dst);
    int n = p ? 8 : 0;
    asm volatile("cp.async.ca.shared.global [%0], [%1], 8, %2;"
                 :: "r"(s), "l"(src), "r"(n));
}
__device__ __forceinline__ void cp_commit() { asm volatile("cp.async.commit_group;"); }
__device__ __forceinline__ void cp_wait0()  { asm volatile("cp.async.wait_group 0;"); }
__device__ __forceinline__ void cp_wait1()  { asm volatile("cp.async.wait_group 1;"); }

// ---------------------------------------------------------------------------
// Fast GEMM (transB): C[M,N] = act( A[M,K] * B[N,K]^T + bias )
// 128x64 block tile, 256 threads, double-buffered cp.async smem + reg frags.
// Optional rowidx: A row gm is read from A[rowidx[gm]] (fused gather).
// ---------------------------------------------------------------------------
__global__ void __launch_bounds__(256, 1)
gemm_f(const float* __restrict__ A, const float* __restrict__ Bm,
       const float* __restrict__ bias,
       float* __restrict__ C, int M, int N, int K, int act,
       const int* __restrict__ rowidx)
{
    extern __shared__ float sm[];
    float* As = sm;                 // [2][128][32]
    float* Bs = sm + 2 * 128 * 32;  // [2][64][32]
    const int tid = threadIdx.x;
    const int tx = tid & 15, ty = tid >> 4;
    const int m0 = blockIdx.y * 128, n0 = blockIdx.x * 64;
    const int nchunks = (K + 31) / 32;

    unsigned long long acc[8][4];
#pragma unroll
    for (int q = 0; q < 8; q++)
#pragma unroll
        for (int p = 0; p < 4; p++) acc[q][p] = 0ull;

    auto stage = [&](int buf, int k0) {
        float* Ab = As + buf * (128 * 32);
        float* Bb = Bs + buf * (64 * 32);
#pragma unroll
        for (int j = 0; j < 4; j++) {
            int idx = tid + 256 * j;
            int r = idx >> 3, kf4 = idx & 7;
            int gm = m0 + r, gk = k0 + kf4 * 4;
            bool pr = (gm < M) && (gk < K);
            int grow = pr ? (rowidx ? rowidx[gm] : gm) : 0;
            const float* src = pr ? (A + (size_t)grow * K + gk) : A;
            cp16(Ab + r * 32 + ((kf4 ^ (r & 7)) << 2), src, pr);
        }
#pragma unroll
        for (int j = 0; j < 2; j++) {
            int idx = tid + 256 * j;
            int r = idx >> 3, kf4 = idx & 7;
            int gn = n0 + r, gk = k0 + kf4 * 4;
            bool pr = (gn < N) && (gk < K);
            const float* src = pr ? (Bm + (size_t)gn * K + gk) : Bm;
            cp16(Bb + r * 32 + ((kf4 ^ (r & 7)) << 2), src, pr);
        }
        cp_commit();
    };

    stage(0, 0);
    int buf = 0;
    for (int c = 0; c < nchunks; c++) {
        cp_wait0();
        __syncthreads();
        if (c + 1 < nchunks) stage(buf ^ 1, (c + 1) * 32);
        const float* Ab = As + buf * (128 * 32);
        const float* Bb = Bs + buf * (64 * 32);

        ulonglong2 a[2][8], b[2][4];
#pragma unroll
        for (int q = 0; q < 8; q++) {
            int r = ty + 16 * q;
            a[0][q] = *reinterpret_cast<const ulonglong2*>(
                Ab + r * 32 + (((0) ^ (r & 7)) << 2));
        }
#pragma unroll
        for (int p = 0; p < 4; p++) {
            int r = tx + 16 * p;
            b[0][p] = *reinterpret_cast<const ulonglong2*>(
                Bb + r * 32 + (((0) ^ (r & 7)) << 2));
        }
#pragma unroll
        for (int k4 = 0; k4 < 8; k4++) {
            const int cur = k4 & 1, nxt = cur ^ 1;
            if (k4 < 7) {
#pragma unroll
                for (int q = 0; q < 8; q++) {
                    int r = ty + 16 * q;
                    a[nxt][q] = *reinterpret_cast<const ulonglong2*>(
                        Ab + r * 32 + (((k4 + 1) ^ (r & 7)) << 2));
                }
#pragma unroll
                for (int p = 0; p < 4; p++) {
                    int r = tx + 16 * p;
                    b[nxt][p] = *reinterpret_cast<const ulonglong2*>(
                        Bb + r * 32 + (((k4 + 1) ^ (r & 7)) << 2));
                }
            }
#pragma unroll
            for (int q = 0; q < 8; q++)
#pragma unroll
                for (int p = 0; p < 4; p++) {
                    acc[q][p] = ffma2(a[cur][q].x, b[cur][p].x, acc[q][p]);
                    acc[q][p] = ffma2(a[cur][q].y, b[cur][p].y, acc[q][p]);
                }
        }
        buf ^= 1;
    }

#pragma unroll
    for (int q = 0; q < 8; q++) {
        int gm = m0 + ty + 16 * q;
        if (gm >= M) continue;
#pragma unroll
        for (int p = 0; p < 4; p++) {
            int gn = n0 + tx + 16 * p;
            if (gn >= N) continue;
            float v = unpack_sum(acc[q][p]);
            if (bias) v += bias[gn];
            if (act == 1) v = fmaxf(v, 0.f);
            C[(size_t)gm * N + gn] = v;
        }
    }
}

// ---------------------------------------------------------------------------
// Both GRU input projections in ONE launch: z selects (x, w, b, out).
// ---------------------------------------------------------------------------
__global__ void __launch_bounds__(256, 1)
gemm_proj(const float* __restrict__ A0, const float* __restrict__ A1,
          const float* __restrict__ B0, const float* __restrict__ B1,
          const float* __restrict__ bias0, const float* __restrict__ bias1,
          float* __restrict__ C0, float* __restrict__ C1)
{
    const int M = BB * SS, N = 3 * HH, K = II;
    const float* A    = blockIdx.z ? A1 : A0;
    const float* Bm   = blockIdx.z ? B1 : B0;
    const float* bias = blockIdx.z ? bias1 : bias0;
    float* C          = blockIdx.z ? C1 : C0;

    extern __shared__ float sm[];
    float* As = sm;
    float* Bs = sm + 2 * 128 * 32;
    const int tid = threadIdx.x;
    const int tx = tid & 15, ty = tid >> 4;
    const int m0 = blockIdx.y * 128, n0 = blockIdx.x * 64;
    const int nchunks = K / 32;   // 4

    unsigned long long acc[8][4];
#pragma unroll
    for (int q = 0; q < 8; q++)
#pragma unroll
        for (int p = 0; p < 4; p++) acc[q][p] = 0ull;

    auto stage = [&](int buf, int k0) {
        float* Ab = As + buf * (128 * 32);
        float* Bb = Bs + buf * (64 * 32);
#pragma unroll
        for (int j = 0; j < 4; j++) {
            int idx = tid + 256 * j;
            int r = idx >> 3, kf4 = idx & 7;
            cp16(Ab + r * 32 + ((kf4 ^ (r & 7)) << 2),
                 A + (size_t)(m0 + r) * K + k0 + kf4 * 4, true);
        }
#pragma unroll
        for (int j = 0; j < 2; j++) {
            int idx = tid + 256 * j;
            int r = idx >> 3, kf4 = idx & 7;
            cp16(Bb + r * 32 + ((kf4 ^ (r & 7)) << 2),
                 Bm + (size_t)(n0 + r) * K + k0 + kf4 * 4, true);
        }
        cp_commit();
    };

    stage(0, 0);
    int buf = 0;
    for (int c = 0; c < nchunks; c++) {
        cp_wait0();
        __syncthreads();
        if (c + 1 < nchunks) stage(buf ^ 1, (c + 1) * 32);
        const float* Ab = As + buf * (128 * 32);
        const float* Bb = Bs + buf * (64 * 32);

        ulonglong2 a[2][8], b[2][4];
#pragma unroll
        for (int q = 0; q < 8; q++) {
            int r = ty + 16 * q;
            a[0][q] = *reinterpret_cast<const ulonglong2*>(
                Ab + r * 32 + (((0) ^ (r & 7)) << 2));
        }
#pragma unroll
        for (int p = 0; p < 4; p++) {
            int r = tx + 16 * p;
            b[0][p] = *reinterpret_cast<const ulonglong2*>(
                Bb + r * 32 + (((0) ^ (r & 7)) << 2));
        }
#pragma unroll
        for (int k4 = 0; k4 < 8; k4++) {
            const int cur = k4 & 1, nxt = cur ^ 1;
            if (k4 < 7) {
#pragma unroll
                for (int q = 0; q < 8; q++) {
                    int r = ty + 16 * q;
                    a[nxt][q] = *reinterpret_cast<const ulonglong2*>(
                        Ab + r * 32 + (((k4 + 1) ^ (r & 7)) << 2));
                }
#pragma unroll
                for (int p = 0; p < 4; p++) {
                    int r = tx + 16 * p;
                    b[nxt][p] = *reinterpret_cast<const ulonglong2*>(
                        Bb + r * 32 + (((k4 + 1) ^ (r & 7)) << 2));
                }
            }
#pragma unroll
            for (int q = 0; q < 8; q++)
#pragma unroll
                for (int p = 0; p < 4; p++) {
                    acc[q][p] = ffma2(a[cur][q].x, b[cur][p].x, acc[q][p]);
                    acc[q][p] = ffma2(a[cur][q].y, b[cur][p].y, acc[q][p]);
                }
        }
        buf ^= 1;
    }

#pragma unroll
    for (int q = 0; q < 8; q++) {
        int gm = m0 + ty + 16 * q;
#pragma unroll
        for (int p = 0; p < 4; p++) {
            int gn = n0 + tx + 16 * p;
            C[(size_t)gm * N + gn] = unpack_sum(acc[q][p]) + bias[gn];
        }
    }
}

// ---------------------------------------------------------------------------
// Small-M GEMM (transB): 64x32 block tile, 128 threads (unchanged).
// ---------------------------------------------------------------------------
__global__ void __launch_bounds__(128)
gemm_s(const float* __restrict__ A, const float* __restrict__ Bm,
       const float* __restrict__ bias, const float* __restrict__ mul,
       float* __restrict__ C, int M, int N, int K, int act)
{
    __shared__ float As[2][64 * 32];
    __shared__ float Bs[2][32 * 32];
    const int tid = threadIdx.x;
    const int tx = tid & 7, ty = tid >> 3;
    const int m0 = blockIdx.y * 64, n0 = blockIdx.x * 32;
    if (n0 >= N) return;
    const int nchunks = (K + 31) / 32;

    unsigned long long acc[4][4];
#pragma unroll
    for (int q = 0; q < 4; q++)
#pragma unroll
        for (int p = 0; p < 4; p++) acc[q][p] = 0ull;

    auto stage = [&](int buf, int k0) {
#pragma unroll
        for (int j = 0; j < 4; j++) {
            int idx = tid + 128 * j;
            int r = idx >> 3, kf4 = idx & 7;
            int gm = m0 + r, gk = k0 + kf4 * 4;
            bool pr = (gm < M) && (gk < K);
            const float* src = pr ? (A + (size_t)gm * K + gk) : A;
            cp16(&As[buf][r * 32 + ((kf4 ^ (r & 7)) << 2)], src, pr);
        }
#pragma unroll
        for (int j = 0; j < 2; j++) {
            int idx = tid + 128 * j;
            int r = idx >> 3, kf4 = idx & 7;
            int gn = n0 + r, gk = k0 + kf4 * 4;
            bool pr = (gn < N) && (gk < K);
            const float* src = pr ? (Bm + (size_t)gn * K + gk) : Bm;
            cp16(&Bs[buf][r * 32 + ((kf4 ^ (r & 7)) << 2)], src, pr);
        }
        cp_commit();
    };

    stage(0, 0);
    int buf = 0;
    for (int c = 0; c < nchunks; c++) {
        cp_wait0();
        __syncthreads();
        if (c + 1 < nchunks) stage(buf ^ 1, (c + 1) * 32);
#pragma unroll
        for (int k4 = 0; k4 < 8; k4++) {
            ulonglong2 a[4], b[4];
#pragma unroll
            for (int q = 0; q < 4; q++) {
                int r = ty + 16 * q;
                a[q] = *reinterpret_cast<const ulonglong2*>(
                    &As[buf][r * 32 + ((k4 ^ (r & 7)) << 2)]);
            }
#pragma unroll
            for (int p = 0; p < 4; p++) {
                int r = tx + 8 * p;
                b[p] = *reinterpret_cast<const ulonglong2*>(
                    &Bs[buf][r * 32 + ((k4 ^ (r & 7)) << 2)]);
            }
#pragma unroll
            for (int q = 0; q < 4; q++)
#pragma unroll
                for (int p = 0; p < 4; p++) {
                    acc[q][p] = ffma2(a[q].x, b[p].x, acc[q][p]);
                    acc[q][p] = ffma2(a[q].y, b[p].y, acc[q][p]);
                }
        }
        buf ^= 1;
    }

#pragma unroll
    for (int q = 0; q < 4; q++) {
        int gm = m0 + ty + 16 * q;
        if (gm >= M) continue;
#pragma unroll
        for (int p = 0; p < 4; p++) {
            int gn = n0 + tx + 8 * p;
            if (gn >= N) continue;
            float v = unpack_sum(acc[q][p]);
            if (bias) v += bias[gn];
            if (act == 1) v = fmaxf(v, 0.f);
            else if (act == 2) v = sigmoidf_(v);
            if (mul) v *= mul[(size_t)gm * N + gn];
            C[(size_t)gm * N + gn] = v;
        }
    }
}

// ---------------------------------------------------------------------------
// Merged tail pair (both consume g_query) — unchanged.
// ---------------------------------------------------------------------------
__global__ void __launch_bounds__(128)
gemm_tail2()
{
    const int z = blockIdx.z;
    const float* Bm   = z ? g_wbipT : g_emb;
    const float* bias = z ? g_bbip  : nullptr;
    float* C          = z ? g_bip   : g_match;
    const int N       = z ? NSUBP   : LBL;
    const int act     = z ? 0       : 2;
    const int M = BB, K = HH;

    __shared__ float As[2][64 * 32];
    __shared__ float Bs[2][32 * 32];
    const int tid = threadIdx.x;
    const int tx = tid & 7, ty = tid >> 3;
    const int m0 = blockIdx.y * 64, n0 = blockIdx.x * 32;
    if (n0 >= N) return;
    const int nchunks = K / 32;

    unsigned long long acc[4][4];
#pragma unroll
    for (int q = 0; q < 4; q++)
#pragma unroll
        for (int p = 0; p < 4; p++) acc[q][p] = 0ull;

    auto stage = [&](int buf, int k0) {
#pragma unroll
        for (int j = 0; j < 4; j++) {
            int idx = tid + 128 * j;
            int r = idx >> 3, kf4 = idx & 7;
            cp16(&As[buf][r * 32 + ((kf4 ^ (r & 7)) << 2)],
                 g_query + (size_t)(m0 + r) * K + k0 + kf4 * 4, true);
        }
#pragma unroll
        for (int j = 0; j < 2; j++) {
            int idx = tid + 128 * j;
            int r = idx >> 3, kf4 = idx & 7;
            int gn = n0 + r;
            bool pr = (gn < N);
            const float* src = pr ? (Bm + (size_t)gn * K + k0 + kf4 * 4) : Bm;
            cp16(&Bs[buf][r * 32 + ((kf4 ^ (r & 7)) << 2)], src, pr);
        }
        cp_commit();
    };

    stage(0, 0);
    int buf = 0;
    for (int c = 0; c < nchunks; c++) {
        cp_wait0();
        __syncthreads();
        if (c + 1 < nchunks) stage(buf ^ 1, (c + 1) * 32);
#pragma unroll
        for (int k4 = 0; k4 < 8; k4++) {
            ulonglong2 a[4], b[4];
#pragma unroll
            for (int q = 0; q < 4; q++) {
                int r = ty + 16 * q;
                a[q] = *reinterpret_cast<const ulonglong2*>(
                    &As[buf][r * 32 + ((k4 ^ (r & 7)) << 2)]);
            }
#pragma unroll
            for (int p = 0; p < 4; p++) {
                int r = tx + 8 * p;
                b[p] = *reinterpret_cast<const ulonglong2*>(
                    &Bs[buf][r * 32 + ((k4 ^ (r & 7)) << 2)]);
            }
#pragma unroll
            for (int q = 0; q < 4; q++)
#pragma unroll
                for (int p = 0; p < 4; p++) {
                    acc[q][p] = ffma2(a[q].x, b[p].x, acc[q][p]);
                    acc[q][p] = ffma2(a[q].y, b[p].y, acc[q][p]);
                }
        }
        buf ^= 1;
    }

#pragma unroll
    for (int q = 0; q < 4; q++) {
        int gm = m0 + ty + 16 * q;
#pragma unroll
        for (int p = 0; p < 4; p++) {
            int gn = n0 + tx + 8 * p;
            if (gn >= N) continue;
            float v = unpack_sum(acc[q][p]);
            if (bias) v += bias[gn];
            if (act == 2) v = sigmoidf_(v);
            C[(size_t)gm * N + gn] = v;
        }
    }
}

// ---------------------------------------------------------------------------
// ONE prep kernel (unchanged; launched on s2)
// ---------------------------------------------------------------------------
__global__ void prep_all_kernel(const int* __restrict__ mask,
                                const int* __restrict__ seg,
                                const float* __restrict__ w_query,
                                const float* __restrict__ w_g0,
                                const float* __restrict__ w_g1,
                                const float* __restrict__ w_bip,
                                const float* __restrict__ w_masklin,
                                const float* __restrict__ ddi,
                                const float* __restrict__ b_bip)
{
    const int gid = blockIdx.x * blockDim.x + threadIdx.x;
    const int stride = gridDim.x * blockDim.x;

    for (int i = gid; i < 2 * BB * HH; i += stride) g_h[0][i] = 0.f;
    for (int i = gid; i < 8 * 32; i += stride) g_bar[i] = 0;
    for (int i = gid; i < BB; i += stride) {
        int s = 0;
        for (int j = 0; j < SS; j++) s += mask[i * SS + j];
        g_idxlast[i] = s - 1;
    }
    for (int i = gid; i < NATOMS; i += stride) {
        if (i == 0) {
            g_molstart[seg[0]] = 0;
            g_molstart[NMOL] = NATOMS;
        } else if (seg[i] != seg[i - 1]) {
            g_molstart[seg[i]] = i;
        }
    }
    for (int i = gid; i < HH * 2 * HH; i += stride) {
        int c = i / (2 * HH), k = i - c * (2 * HH);
        g_wqT[i] = w_query[k * HH + c];
    }
    for (int i = gid; i < HH * HH; i += stride) {
        int c = i / HH, k = i - c * HH;
        g_wg0T[i] = w_g0[k * HH + c];
        g_wg1T[i] = w_g1[k * HH + c];
    }
    for (int i = gid; i < NSUBP * HH; i += stride) {
        int k = i / HH, c = i - k * HH;
        g_wbipT[i] = (k < NSUB) ? w_bip[c * NSUB + k] : 0.f;
    }
    for (int i = gid; i < LBL * NSUBP; i += stride) {
        int j = i / NSUBP, k = i - j * NSUBP;
        g_wmT[i] = (k < NSUB) ? w_masklin[k * LBL + j] * ddi[j * NSUB + k] : 0.f;
    }
    for (int i = gid; i < NSUBP; i += stride)
        g_bbip[i] = (i < NSUB) ? b_bip[i] : 0.f;
}

// ---------------------------------------------------------------------------
// Persistent GRU v2: 128 threads/block, 128 blocks (16 colgroups, 4 bgrp, 2 gru).
// Per thread: 4 batches x 2 cols x 3 gates = 24 FFMA2 per k2, 4 h + 6 w LDS.
// h_s padded to pitch 260 -> conflict-free h loads. FMA-bound inner loop.
// Split-K cp.async staging, xp prefetch before barrier, tid0 busy-spin barrier.
// ---------------------------------------------------------------------------
__global__ void __launch_bounds__(128)
gru_persist_kernel(const float* __restrict__ whh_c, const float* __restrict__ whh_p,
                   const float* __restrict__ bhh_c, const float* __restrict__ bhh_p)
{
    extern __shared__ float sm[];
    float* w_s = sm;                    // [48][258]
    float* h_s = sm + 48 * 258;         // [64][HPITCH]
    const int tid = threadIdx.x;        // 0..127
    const int cg = tid & 7;             // col group 0..7
    const int bq = tid >> 3;            // 0..15
    const int g  = blockIdx.z;
    const int c0 = blockIdx.x * 16;
    const int b0 = blockIdx.y * 64;
    const int grp = blockIdx.y + 4 * blockIdx.z;
    const float* whh = g ? whh_p : whh_c;
    const float* bhh = g ? bhh_p : bhh_c;

    // stage weights once: 48 rows x 128 float2 = 6144 cp8 / 128 threads
#pragma unroll
    for (int j = 0; j < 48; j++) {
        int idx = tid + 128 * j;
        int r = idx >> 7, f2 = idx & 127;
        int grow = (r >> 4) * HH + c0 + (r & 15);
        cp8(w_s + r * 258 + f2 * 2, whh + (size_t)grow * HH + f2 * 2, true);
    }
    cp_commit();

    float bh[2][3];
#pragma unroll
    for (int j = 0; j < 2; j++) {
        int col = c0 + cg + 8 * j;
        bh[j][0] = bhh[col];
        bh[j][1] = bhh[HH + col];
        bh[j][2] = bhh[2 * HH + col];
    }
    const int idxl[4] = {g_idxlast[b0 + bq], g_idxlast[b0 + bq + 16],
                         g_idxlast[b0 + bq + 32], g_idxlast[b0 + bq + 48]};

    auto load_xr = [&](int t, float xr[4][2][3]) {
#pragma unroll
        for (int i = 0; i < 4; i++) {
            int b = b0 + bq + 16 * i;
            const float* xp = g_xp + ((size_t)g * BB * SS + (size_t)b * SS + t) * (3 * HH);
#pragma unroll
            for (int j = 0; j < 2; j++) {
                int col = c0 + cg + 8 * j;
                xr[i][j][0] = __ldg(xp + col);
                xr[i][j][1] = __ldg(xp + HH + col);
                xr[i][j][2] = __ldg(xp + 2 * HH + col);
            }
        }
    };

    float xr[4][2][3];
    load_xr(0, xr);

    for (int t = 0; t < SS; t++) {
        const float* hsrc = g_h[t & 1] + g * (BB * HH);
        // stage h halves: 64 rows x 32 float4 each = 2048 cp16 / 128 = 16/thread
#pragma unroll
        for (int j = 0; j < 16; j++) {
            int idx = tid + 128 * j;
            int r = idx >> 5, f4 = idx & 31;
            cp16(h_s + r * HPITCH + f4 * 4, hsrc + (b0 + r) * HH + f4 * 4, true);
        }
        cp_commit();                                   // group A (K 0..127)
#pragma unroll
        for (int j = 0; j < 16; j++) {
            int idx = tid + 128 * j;
            int r = idx >> 5, f4 = idx & 31;
            cp16(h_s + r * HPITCH + 128 + f4 * 4,
                 hsrc + (b0 + r) * HH + 128 + f4 * 4, true);
        }
        cp_commit();                                   // group B (K 128..255)

        unsigned long long acc[4][2][3];
#pragma unroll
        for (int i = 0; i < 4; i++)
#pragma unroll
            for (int j = 0; j < 2; j++)
#pragma unroll
                for (int gt = 0; gt < 3; gt++) acc[i][j][gt] = 0ull;

        cp_wait1();
        __syncthreads();

#pragma unroll 4
        for (int k2 = 0; k2 < 64; k2++) {
            unsigned long long h2[4], w2[2][3];
#pragma unroll
            for (int i = 0; i < 4; i++)
                h2[i] = lds64(h_s + (bq + 16 * i) * HPITCH + 2 * k2);
#pragma unroll
            for (int j = 0; j < 2; j++)
#pragma unroll
                for (int gt = 0; gt < 3; gt++)
                    w2[j][gt] = lds64(w_s + (gt * 16 + cg + 8 * j) * 258 + 2 * k2);
#pragma unroll
            for (int i = 0; i < 4; i++)
#pragma unroll
                for (int j = 0; j < 2; j++)
#pragma unroll
                    for (int gt = 0; gt < 3; gt++)
                        acc[i][j][gt] = ffma2(h2[i], w2[j][gt], acc[i][j][gt]);
        }

        cp_wait0();
        __syncthreads();

#pragma unroll 4
        for (int k2 = 64; k2 < 128; k2++) {
            unsigned long long h2[4], w2[2][3];
#pragma unroll
            for (int i = 0; i < 4; i++)
                h2[i] = lds64(h_s + (bq + 16 * i) * HPITCH + 2 * k2);
#pragma unroll
            for (int j = 0; j < 2; j++)
#pragma unroll
                for (int gt = 0; gt < 3; gt++)
                    w2[j][gt] = lds64(w_s + (gt * 16 + cg + 8 * j) * 258 + 2 * k2);
#pragma unroll
            for (int i = 0; i < 4; i++)
#pragma unroll
                for (int j = 0; j < 2; j++)
#pragma unroll
                    for (int gt = 0; gt < 3; gt++)
                        acc[i][j][gt] = ffma2(h2[i], w2[j][gt], acc[i][j][gt]);
        }

        float* hdst = g_h[(t + 1) & 1] + g * (BB * HH);
#pragma unroll
        for (int i = 0; i < 4; i++) {
            int b = b0 + bq + 16 * i;
#pragma unroll
            for (int j = 0; j < 2; j++) {
                int col = c0 + cg + 8 * j;
                float hr = unpack_sum(acc[i][j][0]) + bh[j][0];
                float hz = unpack_sum(acc[i][j][1]) + bh[j][1];
                float hn = unpack_sum(acc[i][j][2]) + bh[j][2];
                float r = sigmoidf_(xr[i][j][0] + hr);
                float z = sigmoidf_(xr[i][j][1] + hz);
                float n = tanhf(xr[i][j][2] + r * hn);
                float hp = h_s[(bq + 16 * i) * HPITCH + col];
                float hnew = (1.f - z) * n + z * hp;
                hdst[b * HH + col] = hnew;
                if (t == idxl[i])
                    g_pat[b * (2 * HH) + g * HH + col] = fmaxf(hnew, 0.f);
            }
        }

        if (t + 1 < SS) {
            load_xr(t + 1, xr);                // prefetch next xp BEFORE barrier
            __syncthreads();
            if (tid == 0) {
                __threadfence();
                atomicAdd(&g_bar[grp * 32], 1);
                int tgt = 16 * (t + 1);
                while (*(volatile int*)&g_bar[grp * 32] < tgt) { }
                __threadfence();
            }
            __syncthreads();
        }
    }
}

// ---------------------------------------------------------------------------
// Block-diagonal adjacency pass 1 (unchanged)
// ---------------------------------------------------------------------------
__global__ void adj_kernel(const float* __restrict__ adj) {
    int m = blockIdx.x, tid = threadIdx.x;
    int s = g_molstart[m], e = g_molstart[m + 1];
    int na = e - s;
    __shared__ float hs[14][HH];
    __shared__ float as[14][14];
    for (int a = 0; a < na; a++) hs[a][tid] = g_hv[(s + a) * HH + tid];
    for (int idx = tid; idx < na * na; idx += 256) {
        int i = idx / na, j = idx - i * na;
        as[i][j] = adj[(size_t)(s + i) * NATOMS + (s + j)];
    }
    __syncthreads();
    for (int i = 0; i < na; i++) {
        float acc = hs[i][tid];
        for (int j = 0; j < na; j++) acc = fmaf(as[i][j], hs[j][tid], acc);
        g_v[(s + i) * HH + tid] = acc;
    }
}

// ---------------------------------------------------------------------------
// Fused adjacency pass 2 + segment sum (unchanged)
// ---------------------------------------------------------------------------
__global__ void adj_molsum_kernel(const float* __restrict__ adj) {
    int m = blockIdx.x, tid = threadIdx.x;
    int s = g_molstart[m], e = g_molstart[m + 1];
    int na = e - s;
    __shared__ float hs[14][HH];
    __shared__ float as[14][14];
    for (int a = 0; a < na; a++) hs[a][tid] = g_hv[(s + a) * HH + tid];
    for (int idx = tid; idx < na * na; idx += 256) {
        int i = idx / na, j = idx - i * na;
        as[i][j] = adj[(size_t)(s + i) * NATOMS + (s + j)];
    }
    __syncthreads();
    float sum = 0.f;
    for (int i = 0; i < na; i++) {
        float acc = hs[i][tid];
        for (int j = 0; j < na; j++) acc = fmaf(as[i][j], hs[j][tid], acc);
        sum += acc;
    }
    g_molsumT[tid * NMOL + m] = sum;
}

// ---------------------------------------------------------------------------
// x2 = match + match @ w_out + b_out; layernorm -> g_att (unchanged)
// ---------------------------------------------------------------------------
__global__ void att_kernel(const float* __restrict__ w_out, const float* __restrict__ b_out,
                           const float* __restrict__ gamma, const float* __restrict__ beta)
{
    int b = blockIdx.x, tid = threadIdx.x;
    __shared__ float mrow[LBL];
    __shared__ float red[256];
    if (tid < LBL) mrow[tid] = g_match[b * LBL + tid];
    __syncthreads();
    float x2 = 0.f;
    if (tid < LBL) {
        float acc = 0.f;
        for (int k = 0; k < LBL; k++) acc = fmaf(mrow[k], w_out[k * LBL + tid], acc);
        x2 = mrow[tid] + acc + b_out[tid];
    }
    red[tid] = (tid < LBL) ? x2 : 0.f;
    __syncthreads();
    for (int s2 = 128; s2 > 0; s2 >>= 1) {
        if (tid < s2) red[tid] += red[tid + s2];
        __syncthreads();
    }
    float mean = red[0] * (1.f / LBL);
    __syncthreads();
    float d = x2 - mean;
    red[tid] = (tid < LBL) ? d * d : 0.f;
    __syncthreads();
    for (int s2 = 128; s2 > 0; s2 >>= 1) {
        if (tid < s2) red[tid] += red[tid + s2];
        __syncthreads();
    }
    float var = red[0] * (1.f / LBL);
    if (tid < LBL)
        g_att[b * LBL + tid] = d * rsqrtf(var + 1e-5f) * gamma[tid] + beta[tid];
}

// ---------------------------------------------------------------------------
// Launch orchestration (unchanged from R16)
// ---------------------------------------------------------------------------
extern "C" void kernel_launch(void* const* d_in, const int* in_sizes, int n_in,
                              void* d_out, int out_size) {
    const float* x_c      = (const float*)d_in[0];
    const float* x_p      = (const float*)d_in[1];
    const int*   mask     = (const int*)  d_in[2];
    const float* w_ih_c   = (const float*)d_in[3];
    const float* w_hh_c   = (const float*)d_in[4];
    const float* b_ih_c   = (const float*)d_in[5];
    const float* b_hh_c   = (const float*)d_in[6];
    const float* w_ih_p   = (const float*)d_in[7];
    const float* w_hh_p   = (const float*)d_in[8];
    const float* b_ih_p   = (const float*)d_in[9];
    const float* b_hh_p   = (const float*)d_in[10];
    const float* w_query  = (const float*)d_in[11];
    const float* b_query  = (const float*)d_in[12];
    const float* w_bip    = (const float*)d_in[13];
    const float* b_bip    = (const float*)d_in[14];
    const float* w_mlin   = (const float*)d_in[15];
    const float* ddi      = (const float*)d_in[16];
    const float* embed_fp = (const float*)d_in[17];
    const int*   fp       = (const int*)  d_in[18];
    const float* adj      = (const float*)d_in[19];
    const int*   seg      = (const int*)  d_in[20];
    const float* w_g0     = (const float*)d_in[21];
    const float* b_g0     = (const float*)d_in[22];
    const float* w_g1     = (const float*)d_in[23];
    const float* b_g1     = (const float*)d_in[24];
    const float* avgproj  = (const float*)d_in[25];
    const float* w_out    = (const float*)d_in[26];
    const float* b_out    = (const float*)d_in[27];
    const float* ln_g     = (const float*)d_in[28];
    const float* ln_b     = (const float*)d_in[29];
    float* outp = (float*)d_out;

    float *xp, *pat, *query, *v, *hv, *molsumT, *emb, *wmT, *att, *bip;
    float *wg0T, *wg1T, *wqT;
    cudaGetSymbolAddress((void**)&xp,      g_xp);
    cudaGetSymbolAddress((void**)&pat,     g_pat);
    cudaGetSymbolAddress((void**)&query,   g_query);
    cudaGetSymbolAddress((void**)&v,       g_v);
    cudaGetSymbolAddress((void**)&hv,      g_hv);
    cudaGetSymbolAddress((void**)&molsumT, g_molsumT);
    cudaGetSymbolAddress((void**)&emb,     g_emb);
    cudaGetSymbolAddress((void**)&wmT,     g_wmT);
    cudaGetSymbolAddress((void**)&att,     g_att);
    cudaGetSymbolAddress((void**)&bip,     g_bip);
    cudaGetSymbolAddress((void**)&wg0T,    g_wg0T);
    cudaGetSymbolAddress((void**)&wg1T,    g_wg1T);
    cudaGetSymbolAddress((void**)&wqT,     g_wqT);

    const int GEMMF_SMEM = (2 * 128 * 32 + 2 * 64 * 32) * 4;        // 49152
    const int GRU_SMEM   = (48 * 258 + 64 * HPITCH) * 4;            // 116096

    static cudaStream_t s2 = nullptr;
    static cudaEvent_t evFork = nullptr, evJoin2 = nullptr;
    if (!s2) {
        cudaStreamCreateWithFlags(&s2, cudaStreamNonBlocking);
        cudaEventCreateWithFlags(&evFork, cudaEventDisableTiming);
        cudaEventCreateWithFlags(&evJoin2, cudaEventDisableTiming);
        cudaFuncSetAttribute(gemm_f, cudaFuncAttributeMaxDynamicSharedMemorySize, GEMMF_SMEM);
        cudaFuncSetAttribute(gemm_proj, cudaFuncAttributeMaxDynamicSharedMemorySize, GEMMF_SMEM);
        cudaFuncSetAttribute(gru_persist_kernel, cudaFuncAttributeMaxDynamicSharedMemorySize, GRU_SMEM);
    }

    // fork: s2 runs prep + MPNN; main runs proj concurrently
    cudaEventRecord(evFork, 0);
    cudaStreamWaitEvent(s2, evFork, 0);
    {
        prep_all_kernel<<<296, 256, 0, s2>>>(mask, seg, w_query, w_g0, w_g1, w_bip,
                                             w_mlin, ddi, b_bip);
        dim3 grid(HH / 64, (NATOMS + 127) / 128);
        gemm_f<<<grid, 256, GEMMF_SMEM, s2>>>(embed_fp, wg0T, b_g0, hv,
                                              NATOMS, HH, HH, 1, fp);
        adj_kernel<<<NMOL, HH, 0, s2>>>(adj);
        gemm_f<<<grid, 256, GEMMF_SMEM, s2>>>(v, wg1T, b_g1, hv,
                                              NATOMS, HH, HH, 1, nullptr);
        adj_molsum_kernel<<<NMOL, HH, 0, s2>>>(adj);
        gemm_s<<<dim3(8, 4), 128, 0, s2>>>(avgproj, molsumT, nullptr, nullptr, emb,
                                           LBL, HH, NMOL, 0);
        cudaEventRecord(evJoin2, s2);
    }

    // main: both input projections in one launch (overlaps s2)
    gemm_proj<<<dim3(12, 64, 2), 256, GEMMF_SMEM>>>(
        x_c, x_p, w_ih_c, w_ih_p, b_ih_c, b_ih_p,
        xp, xp + (size_t)BB * SS * 3 * HH);

    // join s2, then persistent GRU owns the chip
    cudaStreamWaitEvent(0, evJoin2, 0);
    gru_persist_kernel<<<dim3(16, 4, 2), 128, GRU_SMEM>>>(w_hh_c, w_hh_p, b_hh_c, b_hh_p);

    // tail (main): query -> (match,bip) -> att -> out
    gemm_s<<<dim3(8, 4), 128>>>(pat, wqT, b_query, nullptr, query, BB, HH, 2 * HH, 0);
    gemm_tail2<<<dim3(16, 4, 2), 128>>>();
    att_kernel<<<BB, 256>>>(w_out, b_out, ln_g, ln_b);
    gemm_s<<<dim3(7, 4), 128>>>(bip, wmT, nullptr, att, outp, BB, LBL, NSUBP, 0);
}